// round 6
// baseline (speedup 1.0000x reference)
#include <cuda_runtime.h>
#include <cuda_fp16.h>
#include <cstdint>

#define DMODEL 1024
#define NHEADS 16
#define DKH    64
#define BATCH  2
#define SEQ    2048
#define MTOT   (BATCH*SEQ)   // 4096

// ---------------- scratch (static __device__, no allocation) ----------------
static __device__ __half g_qh[MTOT*DMODEL];
static __device__ __half g_kh[MTOT*DMODEL];
static __device__ __half g_vh[MTOT*DMODEL];
static __device__ __half g_Wq[DMODEL*DMODEL];
static __device__ __half g_Wk[DMODEL*DMODEL];
static __device__ __half g_Wv[DMODEL*DMODEL];
static __device__ __half g_Wo[DMODEL*DMODEL];
static __device__ __half g_Qp[MTOT*DMODEL];
static __device__ __half g_Kp[MTOT*DMODEL];
static __device__ __half g_Vp[MTOT*DMODEL];
static __device__ __half g_Ao[MTOT*DMODEL];

// ---------------- PTX helpers ----------------
__device__ __forceinline__ uint32_t smem_u32(const void* p) {
    uint32_t a;
    asm("{ .reg .u64 t; cvta.to.shared.u64 t, %1; cvt.u32.u64 %0, t; }" : "=r"(a) : "l"(p));
    return a;
}
__device__ __forceinline__ void cp16(uint32_t dst, const void* src) {
    asm volatile("cp.async.cg.shared.global [%0], [%1], 16;" :: "r"(dst), "l"(src));
}
#define CP_COMMIT() asm volatile("cp.async.commit_group;" ::: "memory")
#define CP_WAIT(n)  asm volatile("cp.async.wait_group %0;" :: "n"(n) : "memory")

#define LDSM_X4(r, addr) \
    asm volatile("ldmatrix.sync.aligned.m8n8.x4.shared.b16 {%0,%1,%2,%3}, [%4];" \
        : "=r"((r)[0]), "=r"((r)[1]), "=r"((r)[2]), "=r"((r)[3]) : "r"(addr))
#define LDSM_T_X4(r, addr) \
    asm volatile("ldmatrix.sync.aligned.m8n8.x4.trans.shared.b16 {%0,%1,%2,%3}, [%4];" \
        : "=r"((r)[0]), "=r"((r)[1]), "=r"((r)[2]), "=r"((r)[3]) : "r"(addr))

#define MMA16816(d, a, b0, b1) \
    asm volatile("mma.sync.aligned.m16n8k16.row.col.f32.f16.f16.f32 " \
        "{%0,%1,%2,%3},{%4,%5,%6,%7},{%8,%9},{%0,%1,%2,%3};" \
        : "+f"((d)[0]), "+f"((d)[1]), "+f"((d)[2]), "+f"((d)[3]) \
        : "r"((a)[0]), "r"((a)[1]), "r"((a)[2]), "r"((a)[3]), "r"(b0), "r"(b1))

__device__ __forceinline__ uint32_t packh2(float lo, float hi) {
    __half2 h = __floats2half2_rn(lo, hi);
    return *(uint32_t*)&h;
}
__device__ __forceinline__ float ex2(float x) {
    float y;
    asm("ex2.approx.ftz.f32 %0, %1;" : "=f"(y) : "f"(x));
    return y;
}

// ---------------- fp32 -> fp16 converts (fused) ----------------
__global__ void f2h_multi(const float* s0, const float* s1, const float* s2, const float* s3,
                          __half* d0, __half* d1, __half* d2, __half* d3, int n)
{
    const float* s; __half* d;
    switch (blockIdx.y) {
        case 0: s = s0; d = d0; break;
        case 1: s = s1; d = d1; break;
        case 2: s = s2; d = d2; break;
        default: s = s3; d = d3; break;
    }
    int i = (blockIdx.x * blockDim.x + threadIdx.x) * 8;
    if (i < n) {
        float4 a = *(const float4*)(s + i);
        float4 b = *(const float4*)(s + i + 4);
        __half h[8] = { __float2half_rn(a.x), __float2half_rn(a.y),
                        __float2half_rn(a.z), __float2half_rn(a.w),
                        __float2half_rn(b.x), __float2half_rn(b.y),
                        __float2half_rn(b.z), __float2half_rn(b.w) };
        *(uint4*)(d + i) = *(uint4*)h;
    }
}

// ================= mma.sync NT GEMM: C[M,N] = A[M,K]*B[N,K]^T + bias =================
// tile 128x64x32, 128 threads (4 warps, 64x32 warp tile), 3-stage cp.async.
constexpr int BM = 128, BN = 64, BK = 32;
constexpr int NK = DMODEL / BK;          // 32
constexpr int LDT = 40;                  // half pitch
constexpr int STAGE_BYTES = (BM + BN) * LDT * 2;   // 15360
constexpr int GEMM_SMEM = 3 * STAGE_BYTES;         // 46080

__device__ __forceinline__ void store2(__half* dst, float v0, float v1) {
    *(__half2*)dst = __floats2half2_rn(v0, v1);
}
__device__ __forceinline__ void store2(float* dst, float v0, float v1) {
    *(float2*)dst = make_float2(v0, v1);
}

template <typename OutT>
__device__ __forceinline__ void gemm_body(const __half* __restrict__ A,
                                          const __half* __restrict__ B,
                                          const float* __restrict__ bias,
                                          OutT* __restrict__ C)
{
    extern __shared__ char smem[];
    const uint32_t sb = smem_u32(smem);
    const int tid  = threadIdx.x;
    const int lane = tid & 31;
    const int warp = tid >> 5;
    const int wm = warp & 1;        // 64-row strip
    const int wn = warp >> 1;       // 32-col strip
    const int bm = blockIdx.y * BM;
    const int bn = blockIdx.x * BN;

    auto load_stage = [&](int st, int k0) {
        uint32_t base  = sb + st * STAGE_BYTES;
        uint32_t baseB = base + BM * LDT * 2;
#pragma unroll
        for (int i = 0; i < 4; i++) {          // A: 512 16B chunks
            int id = tid + i * 128;
            int r = id >> 2, cc = id & 3;
            cp16(base + r * (LDT*2) + cc * 16, A + (size_t)(bm + r) * DMODEL + k0 + cc * 8);
        }
#pragma unroll
        for (int i = 0; i < 2; i++) {          // B: 256 chunks
            int id = tid + i * 128;
            int r = id >> 2, cc = id & 3;
            cp16(baseB + r * (LDT*2) + cc * 16, B + (size_t)(bn + r) * DMODEL + k0 + cc * 8);
        }
    };

    float acc[4][4][4];
#pragma unroll
    for (int i = 0; i < 4; i++)
#pragma unroll
        for (int j = 0; j < 4; j++)
#pragma unroll
            for (int e = 0; e < 4; e++) acc[i][j][e] = 0.0f;

    const uint32_t a_lane = ((wm * 64 + (lane & 15)) * LDT + (lane >> 4) * 8) * 2;
    const uint32_t b_lane = (uint32_t)BM * LDT * 2 +
        ((wn * 32 + (lane & 7) + ((lane >> 4) & 1) * 8) * LDT + ((lane >> 3) & 1) * 8) * 2;

    load_stage(0, 0);  CP_COMMIT();
    load_stage(1, BK); CP_COMMIT();

    int st = 0;
    for (int j = 0; j < NK; j++) {
        CP_WAIT(1);
        __syncthreads();
        if (j + 2 < NK) load_stage((st + 2) % 3, (j + 2) * BK);
        CP_COMMIT();

        const uint32_t abase = sb + st * STAGE_BYTES;
#pragma unroll
        for (int kk = 0; kk < 2; kk++) {
            uint32_t ar[4][4];
#pragma unroll
            for (int mi = 0; mi < 4; mi++)
                LDSM_X4(ar[mi], abase + a_lane + mi * 16 * (LDT*2) + kk * 32);
            uint32_t br[2][4];
#pragma unroll
            for (int p = 0; p < 2; p++)
                LDSM_X4(br[p], abase + b_lane + p * 16 * (LDT*2) + kk * 32);
#pragma unroll
            for (int mi = 0; mi < 4; mi++)
#pragma unroll
                for (int ni = 0; ni < 4; ni++) {
                    const int p = ni >> 1, hi = ni & 1;
                    MMA16816(acc[mi][ni], ar[mi], br[p][hi * 2], br[p][hi * 2 + 1]);
                }
        }
        st = (st + 1) % 3;
    }

    const int rr0 = bm + wm * 64 + (lane >> 2);
    const int cb  = bn + wn * 32 + (lane & 3) * 2;
#pragma unroll
    for (int mi = 0; mi < 4; mi++) {
        const int rA = rr0 + mi * 16;
        OutT* rowA = C + (size_t)rA * DMODEL;
        OutT* rowB = C + (size_t)(rA + 8) * DMODEL;
#pragma unroll
        for (int ni = 0; ni < 4; ni++) {
            const int c = cb + ni * 8;
            const float b0 = bias[c], b1 = bias[c + 1];
            store2(rowA + c, acc[mi][ni][0] + b0, acc[mi][ni][1] + b1);
            store2(rowB + c, acc[mi][ni][2] + b0, acc[mi][ni][3] + b1);
        }
    }
}

__global__ void __launch_bounds__(128)
gemm_qkv(const __half* A0, const __half* A1, const __half* A2,
         const __half* B0, const __half* B1, const __half* B2,
         const float* c0, const float* c1, const float* c2,
         __half* C0, __half* C1, __half* C2)
{
    const __half *A, *B; const float* bi; __half* C;
    switch (blockIdx.z) {
        case 0:  A = A0; B = B0; bi = c0; C = C0; break;
        case 1:  A = A1; B = B1; bi = c1; C = C1; break;
        default: A = A2; B = B2; bi = c2; C = C2; break;
    }
    gemm_body<__half>(A, B, bi, C);
}

__global__ void __launch_bounds__(128)
gemm_out(const __half* __restrict__ A, const __half* __restrict__ B,
         const float* __restrict__ bias, float* __restrict__ C)
{
    gemm_body<float>(A, B, bias, C);
}

// ================= flash attention: 128 threads, 32 q-rows/warp =================
// 4 warps x 32 q-rows = 128 q-tile, kv-tile 64, d=64, double-buffered cp.async.
constexpr int FBM = 128, FBN = 64;
constexpr int QP  = 72;                       // half pitch
constexpr int NIT = SEQ / FBN;                // 32
constexpr int Q_BYTES  = FBM * QP * 2;        // 18432
constexpr int KV_BYTES = FBN * QP * 2;        // 9216
constexpr int FLASH_SMEM = Q_BYTES + 4 * KV_BYTES;  // 55296

__global__ void __launch_bounds__(128)
flash_kernel(const __half* __restrict__ Qp, const __half* __restrict__ Kp,
             const __half* __restrict__ Vp, __half* __restrict__ Out)
{
    extern __shared__ char smraw[];
    const uint32_t sQ = smem_u32(smraw);
    const int tid  = threadIdx.x;
    const int lane = tid & 31;
    const int warp = tid >> 5;             // 0..3, 32 q-rows each
    const int bh   = blockIdx.y;
    const int b    = bh >> 4;
    const int h    = bh & 15;
    const size_t hoff = (size_t)h * DKH;
    const int q0   = blockIdx.x * FBM;

    const __half* Qg = Qp + (size_t)(b * SEQ + q0) * DMODEL + hoff;
    const __half* Kg = Kp + (size_t)(b * SEQ) * DMODEL + hoff;
    const __half* Vg = Vp + (size_t)(b * SEQ) * DMODEL + hoff;

    // ---- load Q tile (128 x 64) ----
#pragma unroll
    for (int i = 0; i < 8; i++) {
        int id = tid + i * 128;
        int r = id >> 3, c = (id & 7) * 8;
        *(uint4*)(smraw + (r * QP + c) * 2) = *(const uint4*)(Qg + (size_t)r * DMODEL + c);
    }

    auto load_kv = [&](int s, int kt) {
        uint32_t kb = sQ + Q_BYTES + s * 2 * KV_BYTES;
        uint32_t vb = kb + KV_BYTES;
#pragma unroll
        for (int i = 0; i < 4; i++) {
            int id = tid + i * 128;
            int r = id >> 3, c = (id & 7) * 8;
            uint32_t so = (r * QP + c) * 2;
            size_t go = (size_t)(kt + r) * DMODEL + c;
            cp16(kb + so, Kg + go);
            cp16(vb + so, Vg + go);
        }
    };

    load_kv(0, 0); CP_COMMIT();
    __syncthreads();

    // ---- Q fragments: 2 M-tiles of 16 rows, held all kernel ----
    uint32_t qf[2][4][4];
#pragma unroll
    for (int mi = 0; mi < 2; mi++) {
        uint32_t qaddr = sQ + ((warp * 32 + mi * 16 + (lane & 15)) * QP + (lane >> 4) * 8) * 2;
#pragma unroll
        for (int kk = 0; kk < 4; kk++) LDSM_X4(qf[mi][kk], qaddr + kk * 32);
    }

    const uint32_t k_row = (lane & 7) + ((lane >> 4) & 1) * 8;
    const uint32_t k_col = ((lane >> 3) & 1) * 8;
    const uint32_t v_row = (lane & 7) + ((lane >> 3) & 1) * 8;
    const uint32_t v_col = (lane >> 4) * 8;

    constexpr float SCALE = 0.125f * 1.4426950408889634f;
    float m[2][2], l[2][2];
#pragma unroll
    for (int mi = 0; mi < 2; mi++) { m[mi][0] = m[mi][1] = -1e30f; l[mi][0] = l[mi][1] = 0.0f; }
    float oacc[2][8][4];
#pragma unroll
    for (int mi = 0; mi < 2; mi++)
#pragma unroll
        for (int n = 0; n < 8; n++)
#pragma unroll
            for (int e = 0; e < 4; e++) oacc[mi][n][e] = 0.0f;

    for (int it = 0; it < NIT; it++) {
        if (it + 1 < NIT) { load_kv((it + 1) & 1, (it + 1) * FBN); CP_COMMIT(); CP_WAIT(1); }
        else              { CP_WAIT(0); }
        __syncthreads();

        const uint32_t kbase = sQ + Q_BYTES + (it & 1) * 2 * KV_BYTES;
        const uint32_t vbase = kbase + KV_BYTES;

        // ---- S = Q K^T : 2 M-tiles share each K fragment ----
        float sacc[2][8][4];
#pragma unroll
        for (int mi = 0; mi < 2; mi++)
#pragma unroll
            for (int n = 0; n < 8; n++)
#pragma unroll
                for (int e = 0; e < 4; e++) sacc[mi][n][e] = 0.0f;
#pragma unroll
        for (int kk = 0; kk < 4; kk++)
#pragma unroll
            for (int p = 0; p < 4; p++) {
                uint32_t kb[4];
                LDSM_X4(kb, kbase + ((p * 16 + k_row) * QP + k_col + kk * 16) * 2);
#pragma unroll
                for (int mi = 0; mi < 2; mi++) {
                    MMA16816(sacc[mi][p * 2],     qf[mi][kk], kb[0], kb[1]);
                    MMA16816(sacc[mi][p * 2 + 1], qf[mi][kk], kb[2], kb[3]);
                }
            }

        // ---- online softmax per M-tile ----
#pragma unroll
        for (int mi = 0; mi < 2; mi++) {
            float mx0 = -1e30f, mx1 = -1e30f;
#pragma unroll
            for (int n = 0; n < 8; n++) {
                mx0 = fmaxf(mx0, fmaxf(sacc[mi][n][0], sacc[mi][n][1]));
                mx1 = fmaxf(mx1, fmaxf(sacc[mi][n][2], sacc[mi][n][3]));
            }
            mx0 = fmaxf(mx0, __shfl_xor_sync(0xffffffffu, mx0, 1));
            mx0 = fmaxf(mx0, __shfl_xor_sync(0xffffffffu, mx0, 2));
            mx1 = fmaxf(mx1, __shfl_xor_sync(0xffffffffu, mx1, 1));
            mx1 = fmaxf(mx1, __shfl_xor_sync(0xffffffffu, mx1, 2));
            const float m0n = fmaxf(m[mi][0], mx0 * SCALE);
            const float m1n = fmaxf(m[mi][1], mx1 * SCALE);
            const float c0 = ex2(m[mi][0] - m0n);
            const float c1 = ex2(m[mi][1] - m1n);
            float s0 = 0.0f, s1 = 0.0f;
#pragma unroll
            for (int n = 0; n < 8; n++) {
                sacc[mi][n][0] = ex2(fmaf(sacc[mi][n][0], SCALE, -m0n));
                sacc[mi][n][1] = ex2(fmaf(sacc[mi][n][1], SCALE, -m0n));
                sacc[mi][n][2] = ex2(fmaf(sacc[mi][n][2], SCALE, -m1n));
                sacc[mi][n][3] = ex2(fmaf(sacc[mi][n][3], SCALE, -m1n));
                s0 += sacc[mi][n][0] + sacc[mi][n][1];
                s1 += sacc[mi][n][2] + sacc[mi][n][3];
            }
            s0 += __shfl_xor_sync(0xffffffffu, s0, 1);
            s0 += __shfl_xor_sync(0xffffffffu, s0, 2);
            s1 += __shfl_xor_sync(0xffffffffu, s1, 1);
            s1 += __shfl_xor_sync(0xffffffffu, s1, 2);
            l[mi][0] = l[mi][0] * c0 + s0;  m[mi][0] = m0n;
            l[mi][1] = l[mi][1] * c1 + s1;  m[mi][1] = m1n;
#pragma unroll
            for (int n = 0; n < 8; n++) {
                oacc[mi][n][0] *= c0; oacc[mi][n][1] *= c0;
                oacc[mi][n][2] *= c1; oacc[mi][n][3] *= c1;
            }
        }

        // ---- O += P V : V fragments shared by both M-tiles ----
#pragma unroll
        for (int kc = 0; kc < 4; kc++) {
            uint32_t pa[2][4];
#pragma unroll
            for (int mi = 0; mi < 2; mi++) {
                pa[mi][0] = packh2(sacc[mi][2*kc][0],   sacc[mi][2*kc][1]);
                pa[mi][1] = packh2(sacc[mi][2*kc][2],   sacc[mi][2*kc][3]);
                pa[mi][2] = packh2(sacc[mi][2*kc+1][0], sacc[mi][2*kc+1][1]);
                pa[mi][3] = packh2(sacc[mi][2*kc+1][2], sacc[mi][2*kc+1][3]);
            }
#pragma unroll
            for (int nn = 0; nn < 4; nn++) {
                uint32_t vb[4];
                LDSM_T_X4(vb, vbase + ((kc * 16 + v_row) * QP + nn * 16 + v_col) * 2);
#pragma unroll
                for (int mi = 0; mi < 2; mi++) {
                    MMA16816(oacc[mi][nn * 2],     pa[mi], vb[0], vb[1]);
                    MMA16816(oacc[mi][nn * 2 + 1], pa[mi], vb[2], vb[3]);
                }
            }
        }
        __syncthreads();
    }

    // ---- normalize + store ----
    const int r = lane >> 2;
#pragma unroll
    for (int mi = 0; mi < 2; mi++) {
        const float i0 = 1.0f / l[mi][0], i1 = 1.0f / l[mi][1];
        const int grow = b * SEQ + q0 + warp * 32 + mi * 16 + r;
        __half* o0 = Out + (size_t)grow * DMODEL + hoff + (lane & 3) * 2;
        __half* o1 = o0 + (size_t)8 * DMODEL;
#pragma unroll
        for (int n = 0; n < 8; n++) {
            *(__half2*)(o0 + n * 8) = __floats2half2_rn(oacc[mi][n][0] * i0, oacc[mi][n][1] * i0);
            *(__half2*)(o1 + n * 8) = __floats2half2_rn(oacc[mi][n][2] * i1, oacc[mi][n][3] * i1);
        }
    }
}

// ================= host launcher =================
extern "C" void kernel_launch(void* const* d_in, const int* in_sizes, int n_in,
                              void* d_out, int out_size)
{
    const float* q  = (const float*)d_in[0];
    const float* k  = (const float*)d_in[1];
    const float* v  = (const float*)d_in[2];
    const float* Wq = (const float*)d_in[4];
    const float* bq = (const float*)d_in[5];
    const float* Wk = (const float*)d_in[6];
    const float* bk = (const float*)d_in[7];
    const float* Wv = (const float*)d_in[8];
    const float* bv = (const float*)d_in[9];
    const float* Wo = (const float*)d_in[10];
    const float* bo = (const float*)d_in[11];
    float* out = (float*)d_out;

    __half *qh, *kh, *vh, *wq, *wk, *wv, *wo, *Qp, *Kp, *Vp, *Ao;
    cudaGetSymbolAddress((void**)&qh, g_qh);
    cudaGetSymbolAddress((void**)&kh, g_kh);
    cudaGetSymbolAddress((void**)&vh, g_vh);
    cudaGetSymbolAddress((void**)&wq, g_Wq);
    cudaGetSymbolAddress((void**)&wk, g_Wk);
    cudaGetSymbolAddress((void**)&wv, g_Wv);
    cudaGetSymbolAddress((void**)&wo, g_Wo);
    cudaGetSymbolAddress((void**)&Qp, g_Qp);
    cudaGetSymbolAddress((void**)&Kp, g_Kp);
    cudaGetSymbolAddress((void**)&Vp, g_Vp);
    cudaGetSymbolAddress((void**)&Ao, g_Ao);

    cudaFuncSetAttribute(flash_kernel, cudaFuncAttributeMaxDynamicSharedMemorySize, FLASH_SMEM);
    cudaFuncSetAttribute(gemm_qkv, cudaFuncAttributeMaxDynamicSharedMemorySize, GEMM_SMEM);
    cudaFuncSetAttribute(gemm_out, cudaFuncAttributeMaxDynamicSharedMemorySize, GEMM_SMEM);

    const int nX = MTOT * DMODEL;
    const int nW = DMODEL * DMODEL;

    dim3 cvB(256);
    f2h_multi<<<dim3(nX / 8 / 256, 3), cvB>>>(q, k, v, nullptr, qh, kh, vh, nullptr, nX);
    f2h_multi<<<dim3(nW / 8 / 256, 4), cvB>>>(Wq, Wk, Wv, Wo, wq, wk, wv, wo, nW);

    dim3 gQKV(DMODEL / BN, MTOT / BM, 3);  // (16, 32, 3)
    gemm_qkv<<<gQKV, 128, GEMM_SMEM>>>(qh, kh, vh, wq, wk, wv, bq, bk, bv, Qp, Kp, Vp);

    dim3 fG(SEQ / FBM, BATCH * NHEADS);    // (16, 32)
    flash_kernel<<<fG, 128, FLASH_SMEM>>>(Qp, Kp, Vp, Ao);

    dim3 gO(DMODEL / BN, MTOT / BM);       // (16, 32)
    gemm_out<<<gO, 128, GEMM_SMEM>>>(Ao, wo, bo, out);
}

// round 7
// speedup vs baseline: 1.4900x; 1.4900x over previous
#include <cuda_runtime.h>
#include <cuda_fp16.h>
#include <cstdint>

#define DMODEL 1024
#define NHEADS 16
#define DKH    64
#define BATCH  2
#define SEQ    2048
#define MTOT   (BATCH*SEQ)   // 4096

// ---------------- scratch (static __device__, no allocation) ----------------
static __device__ __half g_qh[MTOT*DMODEL];
static __device__ __half g_kh[MTOT*DMODEL];
static __device__ __half g_vh[MTOT*DMODEL];
static __device__ __half g_Wq[DMODEL*DMODEL];
static __device__ __half g_Wk[DMODEL*DMODEL];
static __device__ __half g_Wv[DMODEL*DMODEL];
static __device__ __half g_Wo[DMODEL*DMODEL];
static __device__ __half g_Qp[MTOT*DMODEL];
static __device__ __half g_Kp[MTOT*DMODEL];
static __device__ __half g_Vp[MTOT*DMODEL];
static __device__ __half g_Ao[MTOT*DMODEL];

// ---------------- PTX helpers ----------------
__device__ __forceinline__ uint32_t smem_u32(const void* p) {
    uint32_t a;
    asm("{ .reg .u64 t; cvta.to.shared.u64 t, %1; cvt.u32.u64 %0, t; }" : "=r"(a) : "l"(p));
    return a;
}
__device__ __forceinline__ void cp16(uint32_t dst, const void* src) {
    asm volatile("cp.async.cg.shared.global [%0], [%1], 16;" :: "r"(dst), "l"(src));
}
#define CP_COMMIT() asm volatile("cp.async.commit_group;" ::: "memory")
#define CP_WAIT(n)  asm volatile("cp.async.wait_group %0;" :: "n"(n) : "memory")

#define LDSM_X4(r, addr) \
    asm volatile("ldmatrix.sync.aligned.m8n8.x4.shared.b16 {%0,%1,%2,%3}, [%4];" \
        : "=r"((r)[0]), "=r"((r)[1]), "=r"((r)[2]), "=r"((r)[3]) : "r"(addr))
#define LDSM_T_X4(r, addr) \
    asm volatile("ldmatrix.sync.aligned.m8n8.x4.trans.shared.b16 {%0,%1,%2,%3}, [%4];" \
        : "=r"((r)[0]), "=r"((r)[1]), "=r"((r)[2]), "=r"((r)[3]) : "r"(addr))

#define MMA16816(d, a, b0, b1) \
    asm volatile("mma.sync.aligned.m16n8k16.row.col.f32.f16.f16.f32 " \
        "{%0,%1,%2,%3},{%4,%5,%6,%7},{%8,%9},{%0,%1,%2,%3};" \
        : "+f"((d)[0]), "+f"((d)[1]), "+f"((d)[2]), "+f"((d)[3]) \
        : "r"((a)[0]), "r"((a)[1]), "r"((a)[2]), "r"((a)[3]), "r"(b0), "r"(b1))

__device__ __forceinline__ uint32_t packh2(float lo, float hi) {
    __half2 h = __floats2half2_rn(lo, hi);
    return *(uint32_t*)&h;
}
__device__ __forceinline__ float ex2(float x) {
    float y;
    asm("ex2.approx.ftz.f32 %0, %1;" : "=f"(y) : "f"(x));
    return y;
}

// ---------------- fp32 -> fp16 converts (fused) ----------------
__global__ void f2h_multi(const float* s0, const float* s1, const float* s2, const float* s3,
                          __half* d0, __half* d1, __half* d2, __half* d3, int n)
{
    const float* s; __half* d;
    switch (blockIdx.y) {
        case 0: s = s0; d = d0; break;
        case 1: s = s1; d = d1; break;
        case 2: s = s2; d = d2; break;
        default: s = s3; d = d3; break;
    }
    int i = (blockIdx.x * blockDim.x + threadIdx.x) * 8;
    if (i < n) {
        float4 a = *(const float4*)(s + i);
        float4 b = *(const float4*)(s + i + 4);
        __half h[8] = { __float2half_rn(a.x), __float2half_rn(a.y),
                        __float2half_rn(a.z), __float2half_rn(a.w),
                        __float2half_rn(b.x), __float2half_rn(b.y),
                        __float2half_rn(b.z), __float2half_rn(b.w) };
        *(uint4*)(d + i) = *(uint4*)h;
    }
}

// ================= mma.sync NT GEMM: C[M,N] = A[M,K]*B[N,K]^T + bias =================
// tile 128x64x32, 256 threads, 3-stage cp.async. Grid (N/64, M/128 [, 3 for QKV]).
constexpr int BM = 128, BN = 64, BK = 32;
constexpr int NK = DMODEL / BK;          // 32
constexpr int LDT = 40;                  // half pitch
constexpr int STAGE_BYTES = (BM + BN) * LDT * 2;   // 15360
constexpr int GEMM_SMEM = 3 * STAGE_BYTES;         // 46080

__device__ __forceinline__ void store2(__half* dst, float v0, float v1) {
    *(__half2*)dst = __floats2half2_rn(v0, v1);
}
__device__ __forceinline__ void store2(float* dst, float v0, float v1) {
    *(float2*)dst = make_float2(v0, v1);
}

template <typename OutT>
__device__ __forceinline__ void gemm_body(const __half* __restrict__ A,
                                          const __half* __restrict__ B,
                                          const float* __restrict__ bias,
                                          OutT* __restrict__ C)
{
    extern __shared__ char smem[];
    const uint32_t sb = smem_u32(smem);
    const int tid  = threadIdx.x;
    const int lane = tid & 31;
    const int warp = tid >> 5;
    const int wm = warp & 3;        // 32-row strip
    const int wn = warp >> 2;       // 32-col strip
    const int bm = blockIdx.y * BM;
    const int bn = blockIdx.x * BN;

    const int ra0 = (tid + 0)   >> 2, ca0 = (tid + 0)   & 3;
    const int ra1 = (tid + 256) >> 2, ca1 = (tid + 256) & 3;
    const int rb  = tid >> 2,         cbb = tid & 3;

    auto load_stage = [&](int st, int k0) {
        uint32_t base  = sb + st * STAGE_BYTES;
        uint32_t baseB = base + BM * LDT * 2;
        cp16(base  + ra0 * (LDT*2) + ca0 * 16, A + (size_t)(bm + ra0) * DMODEL + k0 + ca0 * 8);
        cp16(base  + ra1 * (LDT*2) + ca1 * 16, A + (size_t)(bm + ra1) * DMODEL + k0 + ca1 * 8);
        cp16(baseB + rb  * (LDT*2) + cbb * 16, B + (size_t)(bn + rb)  * DMODEL + k0 + cbb * 8);
    };

    float acc[2][4][4];
#pragma unroll
    for (int i = 0; i < 2; i++)
#pragma unroll
        for (int j = 0; j < 4; j++)
#pragma unroll
            for (int e = 0; e < 4; e++) acc[i][j][e] = 0.0f;

    const uint32_t a_lane = ((wm * 32 + (lane & 15)) * LDT + (lane >> 4) * 8) * 2;
    const uint32_t b_lane = (uint32_t)BM * LDT * 2 +
        ((wn * 32 + (lane & 7) + ((lane >> 4) & 1) * 8) * LDT + ((lane >> 3) & 1) * 8) * 2;

    load_stage(0, 0);  CP_COMMIT();
    load_stage(1, BK); CP_COMMIT();

    int st = 0;
    for (int j = 0; j < NK; j++) {
        CP_WAIT(1);
        __syncthreads();
        if (j + 2 < NK) load_stage((st + 2) % 3, (j + 2) * BK);
        CP_COMMIT();

        const uint32_t abase = sb + st * STAGE_BYTES;
#pragma unroll
        for (int kk = 0; kk < 2; kk++) {
            uint32_t ar[2][4];
#pragma unroll
            for (int mi = 0; mi < 2; mi++)
                LDSM_X4(ar[mi], abase + a_lane + mi * 16 * (LDT*2) + kk * 32);
            uint32_t br[2][4];
#pragma unroll
            for (int p = 0; p < 2; p++)
                LDSM_X4(br[p], abase + b_lane + p * 16 * (LDT*2) + kk * 32);
#pragma unroll
            for (int mi = 0; mi < 2; mi++)
#pragma unroll
                for (int ni = 0; ni < 4; ni++) {
                    const int p = ni >> 1, hi = ni & 1;
                    MMA16816(acc[mi][ni], ar[mi], br[p][hi * 2], br[p][hi * 2 + 1]);
                }
        }
        st = (st + 1) % 3;
    }

    const int rr0 = bm + wm * 32 + (lane >> 2);
    const int cb  = bn + wn * 32 + (lane & 3) * 2;
#pragma unroll
    for (int mi = 0; mi < 2; mi++) {
        const int rA = rr0 + mi * 16;
        OutT* rowA = C + (size_t)rA * DMODEL;
        OutT* rowB = C + (size_t)(rA + 8) * DMODEL;
#pragma unroll
        for (int ni = 0; ni < 4; ni++) {
            const int c = cb + ni * 8;
            const float b0 = bias[c], b1 = bias[c + 1];
            store2(rowA + c, acc[mi][ni][0] + b0, acc[mi][ni][1] + b1);
            store2(rowB + c, acc[mi][ni][2] + b0, acc[mi][ni][3] + b1);
        }
    }
}

__global__ void __launch_bounds__(256)
gemm_qkv(const __half* A0, const __half* A1, const __half* A2,
         const __half* B0, const __half* B1, const __half* B2,
         const float* c0, const float* c1, const float* c2,
         __half* C0, __half* C1, __half* C2)
{
    const __half *A, *B; const float* bi; __half* C;
    switch (blockIdx.z) {
        case 0:  A = A0; B = B0; bi = c0; C = C0; break;
        case 1:  A = A1; B = B1; bi = c1; C = C1; break;
        default: A = A2; B = B2; bi = c2; C = C2; break;
    }
    gemm_body<__half>(A, B, bi, C);
}

__global__ void __launch_bounds__(256)
gemm_out(const __half* __restrict__ A, const __half* __restrict__ B,
         const float* __restrict__ bias, float* __restrict__ C)
{
    gemm_body<float>(A, B, bias, C);
}

// ================= flash attention: 256 threads, 16 q-rows/warp, 1 barrier/iter =================
constexpr int FBM = 128, FBN = 64;
constexpr int QP  = 72;                       // half pitch
constexpr int NIT = SEQ / FBN;                // 32
constexpr int Q_BYTES  = FBM * QP * 2;        // 18432
constexpr int KV_BYTES = FBN * QP * 2;        // 9216
constexpr int FLASH_SMEM = Q_BYTES + 4 * KV_BYTES;  // 55296

__global__ void __launch_bounds__(256)
flash_kernel(const __half* __restrict__ Qp, const __half* __restrict__ Kp,
             const __half* __restrict__ Vp, __half* __restrict__ Out)
{
    extern __shared__ char smraw[];
    const uint32_t sQ = smem_u32(smraw);
    const int tid  = threadIdx.x;
    const int lane = tid & 31;
    const int warp = tid >> 5;
    const int bh   = blockIdx.y;
    const int b    = bh >> 4;
    const int h    = bh & 15;
    const size_t hoff = (size_t)h * DKH;
    const int q0   = blockIdx.x * FBM;

    const __half* Qg = Qp + (size_t)(b * SEQ + q0) * DMODEL + hoff;
    const __half* Kg = Kp + (size_t)(b * SEQ) * DMODEL + hoff;
    const __half* Vg = Vp + (size_t)(b * SEQ) * DMODEL + hoff;

    // ---- load Q tile (128 x 64) ----
#pragma unroll
    for (int i = 0; i < 4; i++) {
        int id = tid + i * 256;
        int r = id >> 3, c = (id & 7) * 8;
        *(uint4*)(smraw + (r * QP + c) * 2) = *(const uint4*)(Qg + (size_t)r * DMODEL + c);
    }

    auto load_kv = [&](int s, int kt) {
        uint32_t kb = sQ + Q_BYTES + s * 2 * KV_BYTES;
        uint32_t vb = kb + KV_BYTES;
#pragma unroll
        for (int i = 0; i < 2; i++) {
            int id = tid + i * 256;
            int r = id >> 3, c = (id & 7) * 8;
            uint32_t so = (r * QP + c) * 2;
            size_t go = (size_t)(kt + r) * DMODEL + c;
            cp16(kb + so, Kg + go);
            cp16(vb + so, Vg + go);
        }
    };

    load_kv(0, 0); CP_COMMIT();
    __syncthreads();

    // ---- Q fragments (warp's 16 rows), held all kernel ----
    uint32_t qf[4][4];
    {
        uint32_t qaddr = sQ + ((warp * 16 + (lane & 15)) * QP + (lane >> 4) * 8) * 2;
#pragma unroll
        for (int kk = 0; kk < 4; kk++) LDSM_X4(qf[kk], qaddr + kk * 32);
    }

    const uint32_t k_row = (lane & 7) + ((lane >> 4) & 1) * 8;
    const uint32_t k_col = ((lane >> 3) & 1) * 8;
    const uint32_t v_row = (lane & 7) + ((lane >> 3) & 1) * 8;
    const uint32_t v_col = (lane >> 4) * 8;

    constexpr float SCALE = 0.125f * 1.4426950408889634f;
    float m0 = -1e30f, m1 = -1e30f, l0 = 0.0f, l1 = 0.0f;
    float oacc[8][4];
#pragma unroll
    for (int n = 0; n < 8; n++)
#pragma unroll
        for (int e = 0; e < 4; e++) oacc[n][e] = 0.0f;

    for (int it = 0; it < NIT; it++) {
        // wait the in-flight group (loaded last iteration), align all warps,
        // THEN issue the next load (writes the other buffer) — single barrier.
        CP_WAIT(0);
        __syncthreads();
        if (it + 1 < NIT) { load_kv((it + 1) & 1, (it + 1) * FBN); CP_COMMIT(); }

        const uint32_t kbase = sQ + Q_BYTES + (it & 1) * 2 * KV_BYTES;
        const uint32_t vbase = kbase + KV_BYTES;

        // ---- S = Q K^T ----
        float sacc[8][4];
#pragma unroll
        for (int n = 0; n < 8; n++)
#pragma unroll
            for (int e = 0; e < 4; e++) sacc[n][e] = 0.0f;
#pragma unroll
        for (int kk = 0; kk < 4; kk++)
#pragma unroll
            for (int p = 0; p < 4; p++) {
                uint32_t kb[4];
                LDSM_X4(kb, kbase + ((p * 16 + k_row) * QP + k_col + kk * 16) * 2);
                MMA16816(sacc[p * 2],     qf[kk], kb[0], kb[1]);
                MMA16816(sacc[p * 2 + 1], qf[kk], kb[2], kb[3]);
            }

        // ---- online softmax (registers; quad shuffles) ----
        float mx0 = -1e30f, mx1 = -1e30f;
#pragma unroll
        for (int n = 0; n < 8; n++) {
            mx0 = fmaxf(mx0, fmaxf(sacc[n][0], sacc[n][1]));
            mx1 = fmaxf(mx1, fmaxf(sacc[n][2], sacc[n][3]));
        }
        mx0 = fmaxf(mx0, __shfl_xor_sync(0xffffffffu, mx0, 1));
        mx0 = fmaxf(mx0, __shfl_xor_sync(0xffffffffu, mx0, 2));
        mx1 = fmaxf(mx1, __shfl_xor_sync(0xffffffffu, mx1, 1));
        mx1 = fmaxf(mx1, __shfl_xor_sync(0xffffffffu, mx1, 2));
        const float m0n = fmaxf(m0, mx0 * SCALE);
        const float m1n = fmaxf(m1, mx1 * SCALE);
        const float c0 = ex2(m0 - m0n);
        const float c1 = ex2(m1 - m1n);
        float s0 = 0.0f, s1 = 0.0f;
#pragma unroll
        for (int n = 0; n < 8; n++) {
            sacc[n][0] = ex2(fmaf(sacc[n][0], SCALE, -m0n));
            sacc[n][1] = ex2(fmaf(sacc[n][1], SCALE, -m0n));
            sacc[n][2] = ex2(fmaf(sacc[n][2], SCALE, -m1n));
            sacc[n][3] = ex2(fmaf(sacc[n][3], SCALE, -m1n));
            s0 += sacc[n][0] + sacc[n][1];
            s1 += sacc[n][2] + sacc[n][3];
        }
        s0 += __shfl_xor_sync(0xffffffffu, s0, 1);
        s0 += __shfl_xor_sync(0xffffffffu, s0, 2);
        s1 += __shfl_xor_sync(0xffffffffu, s1, 1);
        s1 += __shfl_xor_sync(0xffffffffu, s1, 2);
        l0 = l0 * c0 + s0;  m0 = m0n;
        l1 = l1 * c1 + s1;  m1 = m1n;
#pragma unroll
        for (int n = 0; n < 8; n++) {
            oacc[n][0] *= c0; oacc[n][1] *= c0;
            oacc[n][2] *= c1; oacc[n][3] *= c1;
        }

        // ---- O += P V ----
#pragma unroll
        for (int kc = 0; kc < 4; kc++) {
            uint32_t pa[4];
            pa[0] = packh2(sacc[2*kc][0],   sacc[2*kc][1]);
            pa[1] = packh2(sacc[2*kc][2],   sacc[2*kc][3]);
            pa[2] = packh2(sacc[2*kc+1][0], sacc[2*kc+1][1]);
            pa[3] = packh2(sacc[2*kc+1][2], sacc[2*kc+1][3]);
#pragma unroll
            for (int nn = 0; nn < 4; nn++) {
                uint32_t vb[4];
                LDSM_T_X4(vb, vbase + ((kc * 16 + v_row) * QP + nn * 16 + v_col) * 2);
                MMA16816(oacc[nn * 2],     pa, vb[0], vb[1]);
                MMA16816(oacc[nn * 2 + 1], pa, vb[2], vb[3]);
            }
        }
    }

    // ---- normalize + store ----
    const float i0 = 1.0f / l0, i1 = 1.0f / l1;
    const int r = lane >> 2;
    const int grow = b * SEQ + q0 + warp * 16 + r;
    __half* o0 = Out + (size_t)grow * DMODEL + hoff + (lane & 3) * 2;
    __half* o1 = o0 + (size_t)8 * DMODEL;
#pragma unroll
    for (int n = 0; n < 8; n++) {
        *(__half2*)(o0 + n * 8) = __floats2half2_rn(oacc[n][0] * i0, oacc[n][1] * i0);
        *(__half2*)(o1 + n * 8) = __floats2half2_rn(oacc[n][2] * i1, oacc[n][3] * i1);
    }
}

// ================= host launcher =================
extern "C" void kernel_launch(void* const* d_in, const int* in_sizes, int n_in,
                              void* d_out, int out_size)
{
    const float* q  = (const float*)d_in[0];
    const float* k  = (const float*)d_in[1];
    const float* v  = (const float*)d_in[2];
    const float* Wq = (const float*)d_in[4];
    const float* bq = (const float*)d_in[5];
    const float* Wk = (const float*)d_in[6];
    const float* bk = (const float*)d_in[7];
    const float* Wv = (const float*)d_in[8];
    const float* bv = (const float*)d_in[9];
    const float* Wo = (const float*)d_in[10];
    const float* bo = (const float*)d_in[11];
    float* out = (float*)d_out;

    __half *qh, *kh, *vh, *wq, *wk, *wv, *wo, *Qp, *Kp, *Vp, *Ao;
    cudaGetSymbolAddress((void**)&qh, g_qh);
    cudaGetSymbolAddress((void**)&kh, g_kh);
    cudaGetSymbolAddress((void**)&vh, g_vh);
    cudaGetSymbolAddress((void**)&wq, g_Wq);
    cudaGetSymbolAddress((void**)&wk, g_Wk);
    cudaGetSymbolAddress((void**)&wv, g_Wv);
    cudaGetSymbolAddress((void**)&wo, g_Wo);
    cudaGetSymbolAddress((void**)&Qp, g_Qp);
    cudaGetSymbolAddress((void**)&Kp, g_Kp);
    cudaGetSymbolAddress((void**)&Vp, g_Vp);
    cudaGetSymbolAddress((void**)&Ao, g_Ao);

    cudaFuncSetAttribute(flash_kernel, cudaFuncAttributeMaxDynamicSharedMemorySize, FLASH_SMEM);
    cudaFuncSetAttribute(gemm_qkv, cudaFuncAttributeMaxDynamicSharedMemorySize, GEMM_SMEM);
    cudaFuncSetAttribute(gemm_out, cudaFuncAttributeMaxDynamicSharedMemorySize, GEMM_SMEM);

    const int nX = MTOT * DMODEL;
    const int nW = DMODEL * DMODEL;

    dim3 cvB(256);
    f2h_multi<<<dim3(nX / 8 / 256, 3), cvB>>>(q, k, v, nullptr, qh, kh, vh, nullptr, nX);
    f2h_multi<<<dim3(nW / 8 / 256, 4), cvB>>>(Wq, Wk, Wv, Wo, wq, wk, wv, wo, nW);

    dim3 gQKV(DMODEL / BN, MTOT / BM, 3);  // (16, 32, 3)
    gemm_qkv<<<gQKV, 256, GEMM_SMEM>>>(qh, kh, vh, wq, wk, wv, bq, bk, bv, Qp, Kp, Vp);

    dim3 fG(SEQ / FBM, BATCH * NHEADS);    // (16, 32)
    flash_kernel<<<fG, 256, FLASH_SMEM>>>(Qp, Kp, Vp, Ao);

    dim3 gO(DMODEL / BN, MTOT / BM);       // (16, 32)
    gemm_out<<<gO, 256, GEMM_SMEM>>>(Ao, wo, bo, out);
}

// round 10
// speedup vs baseline: 1.4950x; 1.0034x over previous
#include <cuda_runtime.h>
#include <cuda_fp16.h>
#include <cstdint>

#define DMODEL 1024
#define NHEADS 16
#define DKH    64
#define BATCH  2
#define SEQ    2048
#define MTOT   (BATCH*SEQ)   // 4096

// ---------------- scratch (static __device__, no allocation) ----------------
static __device__ __half g_qh[MTOT*DMODEL];
static __device__ __half g_kh[MTOT*DMODEL];
static __device__ __half g_vh[MTOT*DMODEL];
static __device__ __half g_Wq[DMODEL*DMODEL];
static __device__ __half g_Wk[DMODEL*DMODEL];
static __device__ __half g_Wv[DMODEL*DMODEL];
static __device__ __half g_Wo[DMODEL*DMODEL];
static __device__ __half g_Qp[MTOT*DMODEL];
static __device__ __half g_Kp[MTOT*DMODEL];
static __device__ __half g_Vp[MTOT*DMODEL];
static __device__ __half g_Ao[MTOT*DMODEL];

// ---------------- PTX helpers ----------------
__device__ __forceinline__ uint32_t smem_u32(const void* p) {
    uint32_t a;
    asm("{ .reg .u64 t; cvta.to.shared.u64 t, %1; cvt.u32.u64 %0, t; }" : "=r"(a) : "l"(p));
    return a;
}
__device__ __forceinline__ void cp16(uint32_t dst, const void* src) {
    asm volatile("cp.async.cg.shared.global [%0], [%1], 16;" :: "r"(dst), "l"(src));
}
#define CP_COMMIT() asm volatile("cp.async.commit_group;" ::: "memory")
#define CP_WAIT(n)  asm volatile("cp.async.wait_group %0;" :: "n"(n) : "memory")

#define LDSM_X4(r, addr) \
    asm volatile("ldmatrix.sync.aligned.m8n8.x4.shared.b16 {%0,%1,%2,%3}, [%4];" \
        : "=r"((r)[0]), "=r"((r)[1]), "=r"((r)[2]), "=r"((r)[3]) : "r"(addr))
#define LDSM_T_X4(r, addr) \
    asm volatile("ldmatrix.sync.aligned.m8n8.x4.trans.shared.b16 {%0,%1,%2,%3}, [%4];" \
        : "=r"((r)[0]), "=r"((r)[1]), "=r"((r)[2]), "=r"((r)[3]) : "r"(addr))

#define MMA16816(d, a, b0, b1) \
    asm volatile("mma.sync.aligned.m16n8k16.row.col.f32.f16.f16.f32 " \
        "{%0,%1,%2,%3},{%4,%5,%6,%7},{%8,%9},{%0,%1,%2,%3};" \
        : "+f"((d)[0]), "+f"((d)[1]), "+f"((d)[2]), "+f"((d)[3]) \
        : "r"((a)[0]), "r"((a)[1]), "r"((a)[2]), "r"((a)[3]), "r"(b0), "r"(b1))

__device__ __forceinline__ uint32_t packh2(float lo, float hi) {
    __half2 h = __floats2half2_rn(lo, hi);
    return *(uint32_t*)&h;
}
__device__ __forceinline__ float ex2(float x) {
    float y;
    asm("ex2.approx.ftz.f32 %0, %1;" : "=f"(y) : "f"(x));
    return y;
}

// ---------------- fp32 -> fp16: all 7 tensors in ONE launch ----------------
// grid.y selects the tensor; sizes differ (nX for y<3, nW for y>=3).
__global__ void __launch_bounds__(256)
f2h_all(const float* q, const float* k, const float* v,
        const float* Wq, const float* Wk, const float* Wv, const float* Wo,
        __half* qh, __half* kh, __half* vh,
        __half* wq, __half* wk, __half* wv, __half* wo,
        int nX, int nW)
{
    const float* s; __half* d; int n;
    switch (blockIdx.y) {
        case 0: s = q;  d = qh; n = nX; break;
        case 1: s = k;  d = kh; n = nX; break;
        case 2: s = v;  d = vh; n = nX; break;
        case 3: s = Wq; d = wq; n = nW; break;
        case 4: s = Wk; d = wk; n = nW; break;
        case 5: s = Wv; d = wv; n = nW; break;
        default: s = Wo; d = wo; n = nW; break;
    }
    int i = (blockIdx.x * blockDim.x + threadIdx.x) * 8;
    if (i < n) {
        float4 a = *(const float4*)(s + i);
        float4 b = *(const float4*)(s + i + 4);
        __half h[8] = { __float2half_rn(a.x), __float2half_rn(a.y),
                        __float2half_rn(a.z), __float2half_rn(a.w),
                        __float2half_rn(b.x), __float2half_rn(b.y),
                        __float2half_rn(b.z), __float2half_rn(b.w) };
        *(uint4*)(d + i) = *(uint4*)h;
    }
}

// ================= mma.sync NT GEMM: C[M,N] = A[M,K]*B[N,K]^T + bias =================
// tile 128x64x32, 256 threads, 3-stage cp.async. Grid (N/64, M/128 [, 3 for QKV]).
constexpr int BM = 128, BN = 64, BK = 32;
constexpr int NK = DMODEL / BK;          // 32
constexpr int LDT = 40;                  // half pitch
constexpr int STAGE_BYTES = (BM + BN) * LDT * 2;   // 15360
constexpr int GEMM_SMEM = 3 * STAGE_BYTES;         // 46080

__device__ __forceinline__ void store2(__half* dst, float v0, float v1) {
    *(__half2*)dst = __floats2half2_rn(v0, v1);
}
__device__ __forceinline__ void store2(float* dst, float v0, float v1) {
    *(float2*)dst = make_float2(v0, v1);
}

template <typename OutT>
__device__ __forceinline__ void gemm_body(const __half* __restrict__ A,
                                          const __half* __restrict__ B,
                                          const float* __restrict__ bias,
                                          OutT* __restrict__ C)
{
    extern __shared__ char smem[];
    const uint32_t sb = smem_u32(smem);
    const int tid  = threadIdx.x;
    const int lane = tid & 31;
    const int warp = tid >> 5;
    const int wm = warp & 3;        // 32-row strip
    const int wn = warp >> 2;       // 32-col strip
    const int bm = blockIdx.y * BM;
    const int bn = blockIdx.x * BN;

    const int ra0 = (tid + 0)   >> 2, ca0 = (tid + 0)   & 3;
    const int ra1 = (tid + 256) >> 2, ca1 = (tid + 256) & 3;
    const int rb  = tid >> 2,         cbb = tid & 3;

    auto load_stage = [&](int st, int k0) {
        uint32_t base  = sb + st * STAGE_BYTES;
        uint32_t baseB = base + BM * LDT * 2;
        cp16(base  + ra0 * (LDT*2) + ca0 * 16, A + (size_t)(bm + ra0) * DMODEL + k0 + ca0 * 8);
        cp16(base  + ra1 * (LDT*2) + ca1 * 16, A + (size_t)(bm + ra1) * DMODEL + k0 + ca1 * 8);
        cp16(baseB + rb  * (LDT*2) + cbb * 16, B + (size_t)(bn + rb)  * DMODEL + k0 + cbb * 8);
    };

    float acc[2][4][4];
#pragma unroll
    for (int i = 0; i < 2; i++)
#pragma unroll
        for (int j = 0; j < 4; j++)
#pragma unroll
            for (int e = 0; e < 4; e++) acc[i][j][e] = 0.0f;

    const uint32_t a_lane = ((wm * 32 + (lane & 15)) * LDT + (lane >> 4) * 8) * 2;
    const uint32_t b_lane = (uint32_t)BM * LDT * 2 +
        ((wn * 32 + (lane & 7) + ((lane >> 4) & 1) * 8) * LDT + ((lane >> 3) & 1) * 8) * 2;

    load_stage(0, 0);  CP_COMMIT();
    load_stage(1, BK); CP_COMMIT();

    int st = 0;
    for (int j = 0; j < NK; j++) {
        CP_WAIT(1);
        __syncthreads();
        if (j + 2 < NK) load_stage((st + 2) % 3, (j + 2) * BK);
        CP_COMMIT();

        const uint32_t abase = sb + st * STAGE_BYTES;
#pragma unroll
        for (int kk = 0; kk < 2; kk++) {
            uint32_t ar[2][4];
#pragma unroll
            for (int mi = 0; mi < 2; mi++)
                LDSM_X4(ar[mi], abase + a_lane + mi * 16 * (LDT*2) + kk * 32);
            uint32_t br[2][4];
#pragma unroll
            for (int p = 0; p < 2; p++)
                LDSM_X4(br[p], abase + b_lane + p * 16 * (LDT*2) + kk * 32);
#pragma unroll
            for (int mi = 0; mi < 2; mi++)
#pragma unroll
                for (int ni = 0; ni < 4; ni++) {
                    const int p = ni >> 1, hi = ni & 1;
                    MMA16816(acc[mi][ni], ar[mi], br[p][hi * 2], br[p][hi * 2 + 1]);
                }
        }
        st = (st + 1) % 3;
    }

    const int rr0 = bm + wm * 32 + (lane >> 2);
    const int cb  = bn + wn * 32 + (lane & 3) * 2;
#pragma unroll
    for (int mi = 0; mi < 2; mi++) {
        const int rA = rr0 + mi * 16;
        OutT* rowA = C + (size_t)rA * DMODEL;
        OutT* rowB = C + (size_t)(rA + 8) * DMODEL;
#pragma unroll
        for (int ni = 0; ni < 4; ni++) {
            const int c = cb + ni * 8;
            const float b0 = bias[c], b1 = bias[c + 1];
            store2(rowA + c, acc[mi][ni][0] + b0, acc[mi][ni][1] + b1);
            store2(rowB + c, acc[mi][ni][2] + b0, acc[mi][ni][3] + b1);
        }
    }
}

__global__ void __launch_bounds__(256)
gemm_qkv(const __half* A0, const __half* A1, const __half* A2,
         const __half* B0, const __half* B1, const __half* B2,
         const float* c0, const float* c1, const float* c2,
         __half* C0, __half* C1, __half* C2)
{
    const __half *A, *B; const float* bi; __half* C;
    switch (blockIdx.z) {
        case 0:  A = A0; B = B0; bi = c0; C = C0; break;
        case 1:  A = A1; B = B1; bi = c1; C = C1; break;
        default: A = A2; B = B2; bi = c2; C = C2; break;
    }
    gemm_body<__half>(A, B, bi, C);
}

__global__ void __launch_bounds__(256)
gemm_out(const __half* __restrict__ A, const __half* __restrict__ B,
         const float* __restrict__ bias, float* __restrict__ C)
{
    gemm_body<float>(A, B, bias, C);
}

// ================= flash attention: 256 threads, 16 q-rows/warp, 1 barrier/iter =================
constexpr int FBM = 128, FBN = 64;
constexpr int QP  = 72;                       // half pitch
constexpr int NIT = SEQ / FBN;                // 32
constexpr int Q_BYTES  = FBM * QP * 2;        // 18432
constexpr int KV_BYTES = FBN * QP * 2;        // 9216
constexpr int FLASH_SMEM = Q_BYTES + 4 * KV_BYTES;  // 55296

__global__ void __launch_bounds__(256)
flash_kernel(const __half* __restrict__ Qp, const __half* __restrict__ Kp,
             const __half* __restrict__ Vp, __half* __restrict__ Out)
{
    extern __shared__ char smraw[];
    const uint32_t sQ = smem_u32(smraw);
    const int tid  = threadIdx.x;
    const int lane = tid & 31;
    const int warp = tid >> 5;
    const int bh   = blockIdx.y;
    const int b    = bh >> 4;
    const int h    = bh & 15;
    const size_t hoff = (size_t)h * DKH;
    const int q0   = blockIdx.x * FBM;

    const __half* Qg = Qp + (size_t)(b * SEQ + q0) * DMODEL + hoff;
    const __half* Kg = Kp + (size_t)(b * SEQ) * DMODEL + hoff;
    const __half* Vg = Vp + (size_t)(b * SEQ) * DMODEL + hoff;

    // ---- load Q tile (128 x 64) ----
#pragma unroll
    for (int i = 0; i < 4; i++) {
        int id = tid + i * 256;
        int r = id >> 3, c = (id & 7) * 8;
        *(uint4*)(smraw + (r * QP + c) * 2) = *(const uint4*)(Qg + (size_t)r * DMODEL + c);
    }

    auto load_kv = [&](int s, int kt) {
        uint32_t kb = sQ + Q_BYTES + s * 2 * KV_BYTES;
        uint32_t vb = kb + KV_BYTES;
#pragma unroll
        for (int i = 0; i < 2; i++) {
            int id = tid + i * 256;
            int r = id >> 3, c = (id & 7) * 8;
            uint32_t so = (r * QP + c) * 2;
            size_t go = (size_t)(kt + r) * DMODEL + c;
            cp16(kb + so, Kg + go);
            cp16(vb + so, Vg + go);
        }
    };

    load_kv(0, 0); CP_COMMIT();
    __syncthreads();

    // ---- Q fragments (warp's 16 rows), held all kernel ----
    uint32_t qf[4][4];
    {
        uint32_t qaddr = sQ + ((warp * 16 + (lane & 15)) * QP + (lane >> 4) * 8) * 2;
#pragma unroll
        for (int kk = 0; kk < 4; kk++) LDSM_X4(qf[kk], qaddr + kk * 32);
    }

    const uint32_t k_row = (lane & 7) + ((lane >> 4) & 1) * 8;
    const uint32_t k_col = ((lane >> 3) & 1) * 8;
    const uint32_t v_row = (lane & 7) + ((lane >> 3) & 1) * 8;
    const uint32_t v_col = (lane >> 4) * 8;

    constexpr float SCALE = 0.125f * 1.4426950408889634f;
    float m0 = -1e30f, m1 = -1e30f, l0 = 0.0f, l1 = 0.0f;
    float oacc[8][4];
#pragma unroll
    for (int n = 0; n < 8; n++)
#pragma unroll
        for (int e = 0; e < 4; e++) oacc[n][e] = 0.0f;

    for (int it = 0; it < NIT; it++) {
        // wait in-flight group, align warps, THEN issue next load (other buffer).
        CP_WAIT(0);
        __syncthreads();
        if (it + 1 < NIT) { load_kv((it + 1) & 1, (it + 1) * FBN); CP_COMMIT(); }

        const uint32_t kbase = sQ + Q_BYTES + (it & 1) * 2 * KV_BYTES;
        const uint32_t vbase = kbase + KV_BYTES;

        // ---- S = Q K^T ----
        float sacc[8][4];
#pragma unroll
        for (int n = 0; n < 8; n++)
#pragma unroll
            for (int e = 0; e < 4; e++) sacc[n][e] = 0.0f;
#pragma unroll
        for (int kk = 0; kk < 4; kk++)
#pragma unroll
            for (int p = 0; p < 4; p++) {
                uint32_t kb[4];
                LDSM_X4(kb, kbase + ((p * 16 + k_row) * QP + k_col + kk * 16) * 2);
                MMA16816(sacc[p * 2],     qf[kk], kb[0], kb[1]);
                MMA16816(sacc[p * 2 + 1], qf[kk], kb[2], kb[3]);
            }

        // ---- online softmax (registers; quad shuffles) ----
        float mx0 = -1e30f, mx1 = -1e30f;
#pragma unroll
        for (int n = 0; n < 8; n++) {
            mx0 = fmaxf(mx0, fmaxf(sacc[n][0], sacc[n][1]));
            mx1 = fmaxf(mx1, fmaxf(sacc[n][2], sacc[n][3]));
        }
        mx0 = fmaxf(mx0, __shfl_xor_sync(0xffffffffu, mx0, 1));
        mx0 = fmaxf(mx0, __shfl_xor_sync(0xffffffffu, mx0, 2));
        mx1 = fmaxf(mx1, __shfl_xor_sync(0xffffffffu, mx1, 1));
        mx1 = fmaxf(mx1, __shfl_xor_sync(0xffffffffu, mx1, 2));
        const float m0n = fmaxf(m0, mx0 * SCALE);
        const float m1n = fmaxf(m1, mx1 * SCALE);
        const float c0 = ex2(m0 - m0n);
        const float c1 = ex2(m1 - m1n);
        float s0 = 0.0f, s1 = 0.0f;
#pragma unroll
        for (int n = 0; n < 8; n++) {
            sacc[n][0] = ex2(fmaf(sacc[n][0], SCALE, -m0n));
            sacc[n][1] = ex2(fmaf(sacc[n][1], SCALE, -m0n));
            sacc[n][2] = ex2(fmaf(sacc[n][2], SCALE, -m1n));
            sacc[n][3] = ex2(fmaf(sacc[n][3], SCALE, -m1n));
            s0 += sacc[n][0] + sacc[n][1];
            s1 += sacc[n][2] + sacc[n][3];
        }
        s0 += __shfl_xor_sync(0xffffffffu, s0, 1);
        s0 += __shfl_xor_sync(0xffffffffu, s0, 2);
        s1 += __shfl_xor_sync(0xffffffffu, s1, 1);
        s1 += __shfl_xor_sync(0xffffffffu, s1, 2);
        l0 = l0 * c0 + s0;  m0 = m0n;
        l1 = l1 * c1 + s1;  m1 = m1n;
#pragma unroll
        for (int n = 0; n < 8; n++) {
            oacc[n][0] *= c0; oacc[n][1] *= c0;
            oacc[n][2] *= c1; oacc[n][3] *= c1;
        }

        // ---- O += P V ----
#pragma unroll
        for (int kc = 0; kc < 4; kc++) {
            uint32_t pa[4];
            pa[0] = packh2(sacc[2*kc][0],   sacc[2*kc][1]);
            pa[1] = packh2(sacc[2*kc][2],   sacc[2*kc][3]);
            pa[2] = packh2(sacc[2*kc+1][0], sacc[2*kc+1][1]);
            pa[3] = packh2(sacc[2*kc+1][2], sacc[2*kc+1][3]);
#pragma unroll
            for (int nn = 0; nn < 4; nn++) {
                uint32_t vb[4];
                LDSM_T_X4(vb, vbase + ((kc * 16 + v_row) * QP + nn * 16 + v_col) * 2);
                MMA16816(oacc[nn * 2],     pa, vb[0], vb[1]);
                MMA16816(oacc[nn * 2 + 1], pa, vb[2], vb[3]);
            }
        }
    }

    // ---- normalize + store ----
    const float i0 = 1.0f / l0, i1 = 1.0f / l1;
    const int r = lane >> 2;
    const int grow = b * SEQ + q0 + warp * 16 + r;
    __half* o0 = Out + (size_t)grow * DMODEL + hoff + (lane & 3) * 2;
    __half* o1 = o0 + (size_t)8 * DMODEL;
#pragma unroll
    for (int n = 0; n < 8; n++) {
        *(__half2*)(o0 + n * 8) = __floats2half2_rn(oacc[n][0] * i0, oacc[n][1] * i0);
        *(__half2*)(o1 + n * 8) = __floats2half2_rn(oacc[n][2] * i1, oacc[n][3] * i1);
    }
}

// ================= host launcher =================
extern "C" void kernel_launch(void* const* d_in, const int* in_sizes, int n_in,
                              void* d_out, int out_size)
{
    const float* q  = (const float*)d_in[0];
    const float* k  = (const float*)d_in[1];
    const float* v  = (const float*)d_in[2];
    const float* Wq = (const float*)d_in[4];
    const float* bq = (const float*)d_in[5];
    const float* Wk = (const float*)d_in[6];
    const float* bk = (const float*)d_in[7];
    const float* Wv = (const float*)d_in[8];
    const float* bv = (const float*)d_in[9];
    const float* Wo = (const float*)d_in[10];
    const float* bo = (const float*)d_in[11];
    float* out = (float*)d_out;

    __half *qh, *kh, *vh, *wq, *wk, *wv, *wo, *Qp, *Kp, *Vp, *Ao;
    cudaGetSymbolAddress((void**)&qh, g_qh);
    cudaGetSymbolAddress((void**)&kh, g_kh);
    cudaGetSymbolAddress((void**)&vh, g_vh);
    cudaGetSymbolAddress((void**)&wq, g_Wq);
    cudaGetSymbolAddress((void**)&wk, g_Wk);
    cudaGetSymbolAddress((void**)&wv, g_Wv);
    cudaGetSymbolAddress((void**)&wo, g_Wo);
    cudaGetSymbolAddress((void**)&Qp, g_Qp);
    cudaGetSymbolAddress((void**)&Kp, g_Kp);
    cudaGetSymbolAddress((void**)&Vp, g_Vp);
    cudaGetSymbolAddress((void**)&Ao, g_Ao);

    cudaFuncSetAttribute(flash_kernel, cudaFuncAttributeMaxDynamicSharedMemorySize, FLASH_SMEM);
    cudaFuncSetAttribute(gemm_qkv, cudaFuncAttributeMaxDynamicSharedMemorySize, GEMM_SMEM);
    cudaFuncSetAttribute(gemm_out, cudaFuncAttributeMaxDynamicSharedMemorySize, GEMM_SMEM);

    const int nX = MTOT * DMODEL;     // 4,194,304
    const int nW = DMODEL * DMODEL;   // 1,048,576

    // one launch converts all 7 tensors; slices with i >= n exit immediately
    dim3 cvG(nX / 8 / 256, 7);        // (2048, 7)
    f2h_all<<<cvG, 256>>>(q, k, v, Wq, Wk, Wv, Wo,
                          qh, kh, vh, wq, wk, wv, wo, nX, nW);

    dim3 gQKV(DMODEL / BN, MTOT / BM, 3);  // (16, 32, 3)
    gemm_qkv<<<gQKV, 256, GEMM_SMEM>>>(qh, kh, vh, wq, wk, wv, bq, bk, bv, Qp, Kp, Vp);

    dim3 fG(SEQ / FBM, BATCH * NHEADS);    // (16, 32)
    flash_kernel<<<fG, 256, FLASH_SMEM>>>(Qp, Kp, Vp, Ao);

    dim3 gO(DMODEL / BN, MTOT / BM);       // (16, 32)
    gemm_out<<<gO, 256, GEMM_SMEM>>>(Ao, wo, bo, out);
}

// round 11
// speedup vs baseline: 1.5577x; 1.0419x over previous
#include <cuda_runtime.h>
#include <cuda_fp16.h>
#include <cstdint>

#define DMODEL 1024
#define NHEADS 16
#define DKH    64
#define BATCH  2
#define SEQ    2048
#define MTOT   (BATCH*SEQ)   // 4096

// ---------------- scratch (static __device__, no allocation) ----------------
static __device__ __half g_qh[MTOT*DMODEL];
static __device__ __half g_kh[MTOT*DMODEL];
static __device__ __half g_vh[MTOT*DMODEL];
static __device__ __half g_Wq[DMODEL*DMODEL];
static __device__ __half g_Wk[DMODEL*DMODEL];
static __device__ __half g_Wv[DMODEL*DMODEL];
static __device__ __half g_Wo[DMODEL*DMODEL];
static __device__ __half g_Qp[MTOT*DMODEL];
static __device__ __half g_Kp[MTOT*DMODEL];
static __device__ __half g_Vp[MTOT*DMODEL];
static __device__ __half g_Ao[MTOT*DMODEL];

// ---------------- PTX helpers ----------------
__device__ __forceinline__ uint32_t smem_u32(const void* p) {
    uint32_t a;
    asm("{ .reg .u64 t; cvta.to.shared.u64 t, %1; cvt.u32.u64 %0, t; }" : "=r"(a) : "l"(p));
    return a;
}
__device__ __forceinline__ void cp16(uint32_t dst, const void* src) {
    asm volatile("cp.async.cg.shared.global [%0], [%1], 16;" :: "r"(dst), "l"(src));
}
#define CP_COMMIT() asm volatile("cp.async.commit_group;" ::: "memory")
#define CP_WAIT(n)  asm volatile("cp.async.wait_group %0;" :: "n"(n) : "memory")

#define LDSM_X4(r, addr) \
    asm volatile("ldmatrix.sync.aligned.m8n8.x4.shared.b16 {%0,%1,%2,%3}, [%4];" \
        : "=r"((r)[0]), "=r"((r)[1]), "=r"((r)[2]), "=r"((r)[3]) : "r"(addr))
#define LDSM_T_X4(r, addr) \
    asm volatile("ldmatrix.sync.aligned.m8n8.x4.trans.shared.b16 {%0,%1,%2,%3}, [%4];" \
        : "=r"((r)[0]), "=r"((r)[1]), "=r"((r)[2]), "=r"((r)[3]) : "r"(addr))

#define MMA16816(d, a, b0, b1) \
    asm volatile("mma.sync.aligned.m16n8k16.row.col.f32.f16.f16.f32 " \
        "{%0,%1,%2,%3},{%4,%5,%6,%7},{%8,%9},{%0,%1,%2,%3};" \
        : "+f"((d)[0]), "+f"((d)[1]), "+f"((d)[2]), "+f"((d)[3]) \
        : "r"((a)[0]), "r"((a)[1]), "r"((a)[2]), "r"((a)[3]), "r"(b0), "r"(b1))

__device__ __forceinline__ float ex2(float x) {
    float y;
    asm("ex2.approx.ftz.f32 %0, %1;" : "=f"(y) : "f"(x));
    return y;
}
// pack two f32 -> f16x2 (lo = first arg), then 2^x elementwise in fp16
__device__ __forceinline__ uint32_t cvt_f16x2(float lo, float hi) {
    uint32_t d;
    asm("cvt.rn.f16x2.f32 %0, %1, %2;" : "=r"(d) : "f"(hi), "f"(lo));
    return d;
}
__device__ __forceinline__ uint32_t ex2_f16x2(uint32_t x) {
    uint32_t d;
    asm("ex2.approx.f16x2 %0, %1;" : "=r"(d) : "r"(x));
    return d;
}

// ---------------- fp32 -> fp16: all 7 tensors in ONE launch ----------------
__global__ void __launch_bounds__(256)
f2h_all(const float* q, const float* k, const float* v,
        const float* Wq, const float* Wk, const float* Wv, const float* Wo,
        __half* qh, __half* kh, __half* vh,
        __half* wq, __half* wk, __half* wv, __half* wo,
        int nX, int nW)
{
    const float* s; __half* d; int n;
    switch (blockIdx.y) {
        case 0: s = q;  d = qh; n = nX; break;
        case 1: s = k;  d = kh; n = nX; break;
        case 2: s = v;  d = vh; n = nX; break;
        case 3: s = Wq; d = wq; n = nW; break;
        case 4: s = Wk; d = wk; n = nW; break;
        case 5: s = Wv; d = wv; n = nW; break;
        default: s = Wo; d = wo; n = nW; break;
    }
    int i = (blockIdx.x * blockDim.x + threadIdx.x) * 8;
    if (i < n) {
        float4 a = *(const float4*)(s + i);
        float4 b = *(const float4*)(s + i + 4);
        __half h[8] = { __float2half_rn(a.x), __float2half_rn(a.y),
                        __float2half_rn(a.z), __float2half_rn(a.w),
                        __float2half_rn(b.x), __float2half_rn(b.y),
                        __float2half_rn(b.z), __float2half_rn(b.w) };
        *(uint4*)(d + i) = *(uint4*)h;
    }
}

// ================= mma.sync NT GEMM: C[M,N] = A[M,K]*B[N,K]^T + bias =================
constexpr int BM = 128, BN = 64, BK = 32;
constexpr int NK = DMODEL / BK;          // 32
constexpr int LDT = 40;                  // half pitch
constexpr int STAGE_BYTES = (BM + BN) * LDT * 2;   // 15360
constexpr int GEMM_SMEM = 3 * STAGE_BYTES;         // 46080

__device__ __forceinline__ void store2(__half* dst, float v0, float v1) {
    *(__half2*)dst = __floats2half2_rn(v0, v1);
}
__device__ __forceinline__ void store2(float* dst, float v0, float v1) {
    *(float2*)dst = make_float2(v0, v1);
}

template <typename OutT>
__device__ __forceinline__ void gemm_body(const __half* __restrict__ A,
                                          const __half* __restrict__ B,
                                          const float* __restrict__ bias,
                                          OutT* __restrict__ C)
{
    extern __shared__ char smem[];
    const uint32_t sb = smem_u32(smem);
    const int tid  = threadIdx.x;
    const int lane = tid & 31;
    const int warp = tid >> 5;
    const int wm = warp & 3;
    const int wn = warp >> 2;
    const int bm = blockIdx.y * BM;
    const int bn = blockIdx.x * BN;

    const int ra0 = (tid + 0)   >> 2, ca0 = (tid + 0)   & 3;
    const int ra1 = (tid + 256) >> 2, ca1 = (tid + 256) & 3;
    const int rb  = tid >> 2,         cbb = tid & 3;

    auto load_stage = [&](int st, int k0) {
        uint32_t base  = sb + st * STAGE_BYTES;
        uint32_t baseB = base + BM * LDT * 2;
        cp16(base  + ra0 * (LDT*2) + ca0 * 16, A + (size_t)(bm + ra0) * DMODEL + k0 + ca0 * 8);
        cp16(base  + ra1 * (LDT*2) + ca1 * 16, A + (size_t)(bm + ra1) * DMODEL + k0 + ca1 * 8);
        cp16(baseB + rb  * (LDT*2) + cbb * 16, B + (size_t)(bn + rb)  * DMODEL + k0 + cbb * 8);
    };

    float acc[2][4][4];
#pragma unroll
    for (int i = 0; i < 2; i++)
#pragma unroll
        for (int j = 0; j < 4; j++)
#pragma unroll
            for (int e = 0; e < 4; e++) acc[i][j][e] = 0.0f;

    const uint32_t a_lane = ((wm * 32 + (lane & 15)) * LDT + (lane >> 4) * 8) * 2;
    const uint32_t b_lane = (uint32_t)BM * LDT * 2 +
        ((wn * 32 + (lane & 7) + ((lane >> 4) & 1) * 8) * LDT + ((lane >> 3) & 1) * 8) * 2;

    load_stage(0, 0);  CP_COMMIT();
    load_stage(1, BK); CP_COMMIT();

    int st = 0;
    for (int j = 0; j < NK; j++) {
        CP_WAIT(1);
        __syncthreads();
        if (j + 2 < NK) load_stage((st + 2) % 3, (j + 2) * BK);
        CP_COMMIT();

        const uint32_t abase = sb + st * STAGE_BYTES;
#pragma unroll
        for (int kk = 0; kk < 2; kk++) {
            uint32_t ar[2][4];
#pragma unroll
            for (int mi = 0; mi < 2; mi++)
                LDSM_X4(ar[mi], abase + a_lane + mi * 16 * (LDT*2) + kk * 32);
            uint32_t br[2][4];
#pragma unroll
            for (int p = 0; p < 2; p++)
                LDSM_X4(br[p], abase + b_lane + p * 16 * (LDT*2) + kk * 32);
#pragma unroll
            for (int mi = 0; mi < 2; mi++)
#pragma unroll
                for (int ni = 0; ni < 4; ni++) {
                    const int p = ni >> 1, hi = ni & 1;
                    MMA16816(acc[mi][ni], ar[mi], br[p][hi * 2], br[p][hi * 2 + 1]);
                }
        }
        st = (st + 1) % 3;
    }

    const int rr0 = bm + wm * 32 + (lane >> 2);
    const int cb  = bn + wn * 32 + (lane & 3) * 2;
#pragma unroll
    for (int mi = 0; mi < 2; mi++) {
        const int rA = rr0 + mi * 16;
        OutT* rowA = C + (size_t)rA * DMODEL;
        OutT* rowB = C + (size_t)(rA + 8) * DMODEL;
#pragma unroll
        for (int ni = 0; ni < 4; ni++) {
            const int c = cb + ni * 8;
            const float b0 = bias[c], b1 = bias[c + 1];
            store2(rowA + c, acc[mi][ni][0] + b0, acc[mi][ni][1] + b1);
            store2(rowB + c, acc[mi][ni][2] + b0, acc[mi][ni][3] + b1);
        }
    }
}

__global__ void __launch_bounds__(256)
gemm_qkv(const __half* A0, const __half* A1, const __half* A2,
         const __half* B0, const __half* B1, const __half* B2,
         const float* c0, const float* c1, const float* c2,
         __half* C0, __half* C1, __half* C2)
{
    const __half *A, *B; const float* bi; __half* C;
    switch (blockIdx.z) {
        case 0:  A = A0; B = B0; bi = c0; C = C0; break;
        case 1:  A = A1; B = B1; bi = c1; C = C1; break;
        default: A = A2; B = B2; bi = c2; C = C2; break;
    }
    gemm_body<__half>(A, B, bi, C);
}

__global__ void __launch_bounds__(256)
gemm_out(const __half* __restrict__ A, const __half* __restrict__ B,
         const float* __restrict__ bias, float* __restrict__ C)
{
    gemm_body<float>(A, B, bias, C);
}

// ================= flash attention: f16x2 exp + tensor-core row sums =================
constexpr int FBM = 128, FBN = 64;
constexpr int QP  = 72;
constexpr int NIT = SEQ / FBN;                // 32
constexpr int Q_BYTES  = FBM * QP * 2;        // 18432
constexpr int KV_BYTES = FBN * QP * 2;        // 9216
constexpr int FLASH_SMEM = Q_BYTES + 4 * KV_BYTES;  // 55296
constexpr uint32_t ONES_H2 = 0x3C003C00u;     // half2(1.0, 1.0)

__global__ void __launch_bounds__(256)
flash_kernel(const __half* __restrict__ Qp, const __half* __restrict__ Kp,
             const __half* __restrict__ Vp, __half* __restrict__ Out)
{
    extern __shared__ char smraw[];
    const uint32_t sQ = smem_u32(smraw);
    const int tid  = threadIdx.x;
    const int lane = tid & 31;
    const int warp = tid >> 5;
    const int bh   = blockIdx.y;
    const int b    = bh >> 4;
    const int h    = bh & 15;
    const size_t hoff = (size_t)h * DKH;
    const int q0   = blockIdx.x * FBM;

    const __half* Qg = Qp + (size_t)(b * SEQ + q0) * DMODEL + hoff;
    const __half* Kg = Kp + (size_t)(b * SEQ) * DMODEL + hoff;
    const __half* Vg = Vp + (size_t)(b * SEQ) * DMODEL + hoff;

    // ---- load Q tile (128 x 64) ----
#pragma unroll
    for (int i = 0; i < 4; i++) {
        int id = tid + i * 256;
        int r = id >> 3, c = (id & 7) * 8;
        *(uint4*)(smraw + (r * QP + c) * 2) = *(const uint4*)(Qg + (size_t)r * DMODEL + c);
    }

    auto load_kv = [&](int s, int kt) {
        uint32_t kb = sQ + Q_BYTES + s * 2 * KV_BYTES;
        uint32_t vb = kb + KV_BYTES;
#pragma unroll
        for (int i = 0; i < 2; i++) {
            int id = tid + i * 256;
            int r = id >> 3, c = (id & 7) * 8;
            uint32_t so = (r * QP + c) * 2;
            size_t go = (size_t)(kt + r) * DMODEL + c;
            cp16(kb + so, Kg + go);
            cp16(vb + so, Vg + go);
        }
    };

    load_kv(0, 0); CP_COMMIT();
    __syncthreads();

    // ---- Q fragments (warp's 16 rows), held all kernel ----
    uint32_t qf[4][4];
    {
        uint32_t qaddr = sQ + ((warp * 16 + (lane & 15)) * QP + (lane >> 4) * 8) * 2;
#pragma unroll
        for (int kk = 0; kk < 4; kk++) LDSM_X4(qf[kk], qaddr + kk * 32);
    }

    const uint32_t k_row = (lane & 7) + ((lane >> 4) & 1) * 8;
    const uint32_t k_col = ((lane >> 3) & 1) * 8;
    const uint32_t v_row = (lane & 7) + ((lane >> 3) & 1) * 8;
    const uint32_t v_col = (lane >> 4) * 8;

    constexpr float SCALE = 0.125f * 1.4426950408889634f;
    float m0 = -1e30f, m1 = -1e30f, l0 = 0.0f, l1 = 0.0f;
    float oacc[8][4];
#pragma unroll
    for (int n = 0; n < 8; n++)
#pragma unroll
        for (int e = 0; e < 4; e++) oacc[n][e] = 0.0f;

    for (int it = 0; it < NIT; it++) {
        CP_WAIT(0);
        __syncthreads();
        if (it + 1 < NIT) { load_kv((it + 1) & 1, (it + 1) * FBN); CP_COMMIT(); }

        const uint32_t kbase = sQ + Q_BYTES + (it & 1) * 2 * KV_BYTES;
        const uint32_t vbase = kbase + KV_BYTES;

        // ---- S = Q K^T ----
        float sacc[8][4];
#pragma unroll
        for (int n = 0; n < 8; n++)
#pragma unroll
            for (int e = 0; e < 4; e++) sacc[n][e] = 0.0f;
#pragma unroll
        for (int kk = 0; kk < 4; kk++)
#pragma unroll
            for (int p = 0; p < 4; p++) {
                uint32_t kb[4];
                LDSM_X4(kb, kbase + ((p * 16 + k_row) * QP + k_col + kk * 16) * 2);
                MMA16816(sacc[p * 2],     qf[kk], kb[0], kb[1]);
                MMA16816(sacc[p * 2 + 1], qf[kk], kb[2], kb[3]);
            }

        // ---- online softmax: max in f32, exp in f16x2 ----
        float mx0 = -1e30f, mx1 = -1e30f;
#pragma unroll
        for (int n = 0; n < 8; n++) {
            mx0 = fmaxf(mx0, fmaxf(sacc[n][0], sacc[n][1]));
            mx1 = fmaxf(mx1, fmaxf(sacc[n][2], sacc[n][3]));
        }
        mx0 = fmaxf(mx0, __shfl_xor_sync(0xffffffffu, mx0, 1));
        mx0 = fmaxf(mx0, __shfl_xor_sync(0xffffffffu, mx0, 2));
        mx1 = fmaxf(mx1, __shfl_xor_sync(0xffffffffu, mx1, 1));
        mx1 = fmaxf(mx1, __shfl_xor_sync(0xffffffffu, mx1, 2));
        const float m0n = fmaxf(m0, mx0 * SCALE);
        const float m1n = fmaxf(m1, mx1 * SCALE);
        const float c0 = ex2(m0 - m0n);
        const float c1 = ex2(m1 - m1n);

        // P = 2^(S*SCALE - m) directly in fp16 pairs (rows r -> pp, r+8 -> qq)
        uint32_t pp[8], qq[8];
#pragma unroll
        for (int n = 0; n < 8; n++) {
            float x0 = fmaf(sacc[n][0], SCALE, -m0n);
            float x1 = fmaf(sacc[n][1], SCALE, -m0n);
            float x2 = fmaf(sacc[n][2], SCALE, -m1n);
            float x3 = fmaf(sacc[n][3], SCALE, -m1n);
            pp[n] = ex2_f16x2(cvt_f16x2(x0, x1));
            qq[n] = ex2_f16x2(cvt_f16x2(x2, x3));
        }

        // row sums via tensor core: P(16x64) x ones(64x8) -> exact f32 row sums
        float lacc[4] = { 0.0f, 0.0f, 0.0f, 0.0f };
#pragma unroll
        for (int kc = 0; kc < 4; kc++) {
            uint32_t pa[4] = { pp[2*kc], qq[2*kc], pp[2*kc+1], qq[2*kc+1] };
            MMA16816(lacc, pa, ONES_H2, ONES_H2);
        }
        l0 = l0 * c0 + lacc[0];  m0 = m0n;
        l1 = l1 * c1 + lacc[2];  m1 = m1n;
#pragma unroll
        for (int n = 0; n < 8; n++) {
            oacc[n][0] *= c0; oacc[n][1] *= c0;
            oacc[n][2] *= c1; oacc[n][3] *= c1;
        }

        // ---- O += P V ----
#pragma unroll
        for (int kc = 0; kc < 4; kc++) {
            uint32_t pa[4] = { pp[2*kc], qq[2*kc], pp[2*kc+1], qq[2*kc+1] };
#pragma unroll
            for (int nn = 0; nn < 4; nn++) {
                uint32_t vb[4];
                LDSM_T_X4(vb, vbase + ((kc * 16 + v_row) * QP + nn * 16 + v_col) * 2);
                MMA16816(oacc[nn * 2],     pa, vb[0], vb[1]);
                MMA16816(oacc[nn * 2 + 1], pa, vb[2], vb[3]);
            }
        }
    }

    // ---- normalize + store ----
    const float i0 = 1.0f / l0, i1 = 1.0f / l1;
    const int r = lane >> 2;
    const int grow = b * SEQ + q0 + warp * 16 + r;
    __half* o0 = Out + (size_t)grow * DMODEL + hoff + (lane & 3) * 2;
    __half* o1 = o0 + (size_t)8 * DMODEL;
#pragma unroll
    for (int n = 0; n < 8; n++) {
        *(__half2*)(o0 + n * 8) = __floats2half2_rn(oacc[n][0] * i0, oacc[n][1] * i0);
        *(__half2*)(o1 + n * 8) = __floats2half2_rn(oacc[n][2] * i1, oacc[n][3] * i1);
    }
}

// ================= host launcher =================
extern "C" void kernel_launch(void* const* d_in, const int* in_sizes, int n_in,
                              void* d_out, int out_size)
{
    const float* q  = (const float*)d_in[0];
    const float* k  = (const float*)d_in[1];
    const float* v  = (const float*)d_in[2];
    const float* Wq = (const float*)d_in[4];
    const float* bq = (const float*)d_in[5];
    const float* Wk = (const float*)d_in[6];
    const float* bk = (const float*)d_in[7];
    const float* Wv = (const float*)d_in[8];
    const float* bv = (const float*)d_in[9];
    const float* Wo = (const float*)d_in[10];
    const float* bo = (const float*)d_in[11];
    float* out = (float*)d_out;

    __half *qh, *kh, *vh, *wq, *wk, *wv, *wo, *Qp, *Kp, *Vp, *Ao;
    cudaGetSymbolAddress((void**)&qh, g_qh);
    cudaGetSymbolAddress((void**)&kh, g_kh);
    cudaGetSymbolAddress((void**)&vh, g_vh);
    cudaGetSymbolAddress((void**)&wq, g_Wq);
    cudaGetSymbolAddress((void**)&wk, g_Wk);
    cudaGetSymbolAddress((void**)&wv, g_Wv);
    cudaGetSymbolAddress((void**)&wo, g_Wo);
    cudaGetSymbolAddress((void**)&Qp, g_Qp);
    cudaGetSymbolAddress((void**)&Kp, g_Kp);
    cudaGetSymbolAddress((void**)&Vp, g_Vp);
    cudaGetSymbolAddress((void**)&Ao, g_Ao);

    cudaFuncSetAttribute(flash_kernel, cudaFuncAttributeMaxDynamicSharedMemorySize, FLASH_SMEM);
    cudaFuncSetAttribute(gemm_qkv, cudaFuncAttributeMaxDynamicSharedMemorySize, GEMM_SMEM);
    cudaFuncSetAttribute(gemm_out, cudaFuncAttributeMaxDynamicSharedMemorySize, GEMM_SMEM);

    const int nX = MTOT * DMODEL;     // 4,194,304
    const int nW = DMODEL * DMODEL;   // 1,048,576

    dim3 cvG(nX / 8 / 256, 7);        // (2048, 7)
    f2h_all<<<cvG, 256>>>(q, k, v, Wq, Wk, Wv, Wo,
                          qh, kh, vh, wq, wk, wv, wo, nX, nW);

    dim3 gQKV(DMODEL / BN, MTOT / BM, 3);  // (16, 32, 3)
    gemm_qkv<<<gQKV, 256, GEMM_SMEM>>>(qh, kh, vh, wq, wk, wv, bq, bk, bv, Qp, Kp, Vp);

    dim3 fG(SEQ / FBM, BATCH * NHEADS);    // (16, 32)
    flash_kernel<<<fG, 256, FLASH_SMEM>>>(Qp, Kp, Vp, Ao);

    dim3 gO(DMODEL / BN, MTOT / BM);       // (16, 32)
    gemm_out<<<gO, 256, GEMM_SMEM>>>(Ao, wo, bo, out);
}